// round 2
// baseline (speedup 1.0000x reference)
#include <cuda_runtime.h>
#include <math.h>

#define N_BOX     1048576
#define NUM_PTS   9
#define L_CONST   3.0f
#define EPS_F     1e-6f
#define GMM_EPS_F 1e-6f

__global__ void zero_out_kernel(float* out) {
    out[0] = 0.0f;
}

__global__ void __launch_bounds__(256) kld_loss_kernel(
    const float* __restrict__ pred,    // [N, 9, 2]
    const float* __restrict__ target,  // [N, 4, 2]
    float* __restrict__ out)
{
    const int i = blockIdx.x * blockDim.x + threadIdx.x;

    float loss = 0.0f;
    if (i < N_BOX) {
        // ---- load pred: 9 points, 18 floats, 8B-aligned -> float2 loads ----
        const float2* p2 = reinterpret_cast<const float2*>(pred + (size_t)i * 18);
        float px[NUM_PTS], py[NUM_PTS];
        #pragma unroll
        for (int k = 0; k < NUM_PTS; k++) {
            float2 v = p2[k];
            px[k] = v.x; py[k] = v.y;
        }

        // ---- load target: 4 corners, 8 floats, 32B-aligned -> float4 ----
        const float4* t4 = reinterpret_cast<const float4*>(target + (size_t)i * 8);
        float4 ta = t4[0];   // (t0x, t0y, t1x, t1y)
        float4 tb = t4[1];   // (t2x, t2y, t3x, t3y)

        // ---- pred mean & covariance ----
        float sx = 0.f, sy = 0.f;
        #pragma unroll
        for (int k = 0; k < NUM_PTS; k++) { sx += px[k]; sy += py[k]; }
        const float inv_np = 1.0f / (float)NUM_PTS;
        float mux = sx * inv_np, muy = sy * inv_np;

        float cxx = 0.f, cxy = 0.f, cyy = 0.f;
        #pragma unroll
        for (int k = 0; k < NUM_PTS; k++) {
            float dx = px[k] - mux, dy = py[k] - muy;
            cxx += dx * dx; cxy += dx * dy; cyy += dy * dy;
        }
        cxx = cxx * inv_np + GMM_EPS_F;
        cxy = cxy * inv_np;
        cyy = cyy * inv_np + GMM_EPS_F;

        // ---- target mean ----
        float tmux = (ta.x + ta.z + tb.x + tb.z) * 0.25f;
        float tmuy = (ta.y + ta.w + tb.y + tb.w) * 0.25f;

        // edges
        float e1x = ta.z - ta.x, e1y = ta.w - ta.y;   // t1 - t0
        float e2x = tb.x - ta.z, e2y = tb.y - ta.w;   // t2 - t1
        float w = e1x * e1x + e1y * e1y;
        float h = e2x * e2x + e2y * e2y;
        float inv_sw = rsqrtf(w);
        float c = e1x * inv_sw, s = e1y * inv_sw;

        const float dscale = 1.0f / (4.0f * L_CONST * L_CONST);
        float d0 = w * dscale, d1 = h * dscale;

        // t_var = R diag(d) R^T
        float c2 = c * c, s2 = s * s, cs = c * s;
        float t00 = c2 * d0 + s2 * d1;
        float t01 = cs * (d0 - d1);
        float t11 = s2 * d0 + c2 * d1;

        float t_det = t00 * t11 - t01 * t01;
        float p_det = cxx * cyy - cxy * cxy;

        // t_inv = adj / t_det
        float inv_tdet = 1.0f / t_det;
        float i00 =  t11 * inv_tdet;
        float i01 = -t01 * inv_tdet;
        float i11 =  t00 * inv_tdet;

        float dx = mux - tmux, dy = muy - tmuy;
        float term1 = dx * (i00 * dx + i01 * dy) + dy * (i01 * dx + i11 * dy);

        // trace(t_inv * p_var)  (both symmetric)
        float trace = i00 * cxx + 2.0f * i01 * cxy + i11 * cyy;

        float term2 = trace + logf(t_det / p_det);
        float kld = 0.5f * (term1 + term2) - 1.0f;
        float kl_agg = fmaxf(kld, EPS_F);
        loss = 1.0f - 1.0f / (2.0f + sqrtf(kl_agg));
    }

    // ---- block reduction ----
    // warp shuffle reduce
    #pragma unroll
    for (int off = 16; off > 0; off >>= 1)
        loss += __shfl_down_sync(0xFFFFFFFFu, loss, off);

    __shared__ float warp_sums[8];
    int lane = threadIdx.x & 31;
    int wid  = threadIdx.x >> 5;
    if (lane == 0) warp_sums[wid] = loss;
    __syncthreads();

    if (wid == 0) {
        float v = (lane < 8) ? warp_sums[lane] : 0.0f;
        #pragma unroll
        for (int off = 4; off > 0; off >>= 1)
            v += __shfl_down_sync(0xFFFFFFFFu, v, off);
        if (lane == 0)
            atomicAdd(out, v * (1.0f / (float)N_BOX));
    }
}

extern "C" void kernel_launch(void* const* d_in, const int* in_sizes, int n_in,
                              void* d_out, int out_size) {
    const float* pred   = (const float*)d_in[0];
    const float* target = (const float*)d_in[1];
    float* out = (float*)d_out;

    zero_out_kernel<<<1, 1>>>(out);
    const int threads = 256;
    const int blocks  = (N_BOX + threads - 1) / threads;
    kld_loss_kernel<<<blocks, threads>>>(pred, target, out);
}